// round 2
// baseline (speedup 1.0000x reference)
#include <cuda_runtime.h>

#define BATCH 262144
#define DIM   128
#define K     10
#define NBLK1 512
#define ROWS_PER_BLK (BATCH / NBLK1)   // 512 rows, 16 passes of 32

// Per-block column-sum partials (fully overwritten each replay; no init needed).
__device__ float g_part[NBLK1][K];

typedef unsigned long long u64;

__device__ __forceinline__ u64 pack2(float lo, float hi) {
    u64 r; asm("mov.b64 %0, {%1, %2};" : "=l"(r) : "f"(lo), "f"(hi)); return r;
}
__device__ __forceinline__ void unpack2(u64 v, float& lo, float& hi) {
    asm("mov.b64 {%0, %1}, %2;" : "=f"(lo), "=f"(hi) : "l"(v));
}
__device__ __forceinline__ void fma2(u64& acc, u64 a, u64 b) {
    asm("fma.rn.f32x2 %0, %1, %2, %0;" : "+l"(acc) : "l"(a), "l"(b));
}

// Kernel 1: q = rownorm( 1/(1+||z-mu||^2) ), plus per-block column partials.
// Warp layout: 4 rows per warp, 8 lanes per row (lane = rsub*8 + chunk).
// z loads: each LDG.128 covers 4 rows x 128B contiguous -> fully coalesced.
__global__ __launch_bounds__(256) void k_q(
    const float* __restrict__ z,
    const float* __restrict__ c,
    float* __restrict__ qout)
{
    __shared__ float s_c[K][DIM];     // centers (row-major, 5120 B)
    __shared__ float s_cn[K];         // ||c_j||^2
    __shared__ float s_part[8][K];    // per-warp colsum partials

    const int tid   = threadIdx.x;
    const int lane  = tid & 31;
    const int wrp   = tid >> 5;
    const int chunk = lane & 7;       // which 16 columns of the row
    const int rsub  = lane >> 3;      // which of the warp's 4 rows

    for (int i = tid; i < K * DIM / 4; i += 256)
        ((float4*)s_c)[i] = ((const float4*)c)[i];
    __syncthreads();
    if (tid < K) {
        float s = 0.0f;
        #pragma unroll 8
        for (int d = 0; d < DIM; d++) { float v = s_c[tid][d]; s = fmaf(v, v, s); }
        s_cn[tid] = s;
    }
    __syncthreads();

    float csum[K];
    #pragma unroll
    for (int j = 0; j < K; j++) csum[j] = 0.0f;

    const int base = blockIdx.x * ROWS_PER_BLK;

    for (int pass = 0; pass < ROWS_PER_BLK / 32; pass++) {
        const int row = base + pass * 32 + wrp * 4 + rsub;
        // float4 index within row: chunk + s*8  (columns chunk*4 + s*32 ..+3)
        const float4* zp = (const float4*)(z + (size_t)row * DIM) + chunk;

        float4 zv[4];
        #pragma unroll
        for (int s = 0; s < 4; s++) zv[s] = zp[s * 8];   // front-batched, MLP=4

        u64 dot[K];
        #pragma unroll
        for (int j = 0; j < K; j++) dot[j] = 0ull;
        u64 zn = 0ull;

        #pragma unroll
        for (int s = 0; s < 4; s++) {
            u64 a01 = pack2(zv[s].x, zv[s].y), a23 = pack2(zv[s].z, zv[s].w);
            fma2(zn, a01, a01); fma2(zn, a23, a23);
            #pragma unroll
            for (int j = 0; j < K; j++) {
                float4 cc = ((const float4*)s_c[j])[chunk + s * 8];
                u64 c01 = pack2(cc.x, cc.y), c23 = pack2(cc.z, cc.w);
                fma2(dot[j], a01, c01); fma2(dot[j], a23, c23);
            }
        }

        float lo, hi;
        unpack2(zn, lo, hi);
        float zz = lo + hi;
        #pragma unroll
        for (int m = 1; m < 8; m <<= 1) zz += __shfl_xor_sync(0xFFFFFFFFu, zz, m);

        float q[K], rsum = 0.0f;
        #pragma unroll
        for (int j = 0; j < K; j++) {
            unpack2(dot[j], lo, hi);
            float d = lo + hi;
            #pragma unroll
            for (int m = 1; m < 8; m <<= 1) d += __shfl_xor_sync(0xFFFFFFFFu, d, m);
            // 1 + ||z||^2 - 2 z.c + ||c||^2
            float v = __fdividef(1.0f, fmaf(-2.0f, d, (1.0f + zz) + s_cn[j]));
            q[j] = v; rsum += v;
        }
        const float inv = __fdividef(1.0f, rsum);
        #pragma unroll
        for (int j = 0; j < K; j++) { q[j] *= inv; csum[j] += q[j]; }

        // Store q: pair pj written by the lane with chunk==pj (static reg indices).
        float* orow = qout + (size_t)row * K;
        #pragma unroll
        for (int pj = 0; pj < 5; pj++) {
            if (chunk == pj) {
                float2 v; v.x = q[2 * pj]; v.y = q[2 * pj + 1];
                *(float2*)(orow + 2 * pj) = v;
            }
        }
    }

    // csum counted each row 8x (all 8 lanes of a row added it) -> scale by 1/8.
    #pragma unroll
    for (int j = 0; j < K; j++) {
        float v = csum[j];
        #pragma unroll
        for (int m = 1; m < 32; m <<= 1) v += __shfl_xor_sync(0xFFFFFFFFu, v, m);
        if (lane == j) s_part[wrp][j] = v;
    }
    __syncthreads();
    if (tid < K) {
        float s = 0.0f;
        #pragma unroll
        for (int w = 0; w < 8; w++) s += s_part[w][tid];
        g_part[blockIdx.x][tid] = s * 0.125f;
    }
}

// Kernel 2: reduce partials (redundantly per block), then p = rownorm(q^2 / colsum).
__global__ __launch_bounds__(256) void k_p(
    const float* __restrict__ q,
    float* __restrict__ p)
{
    __shared__ float s_w[8][K];
    __shared__ float s_invf[K];

    const int tid  = threadIdx.x;
    const int lane = tid & 31;
    const int wrp  = tid >> 5;

    float acc[K];
    #pragma unroll
    for (int j = 0; j < K; j++) acc[j] = 0.0f;
    #pragma unroll
    for (int r = 0; r < NBLK1 / 256; r++) {
        const float* gp = g_part[tid + r * 256];
        #pragma unroll
        for (int j = 0; j < K; j++) acc[j] += gp[j];
    }
    #pragma unroll
    for (int j = 0; j < K; j++) {
        float v = acc[j];
        #pragma unroll
        for (int m = 1; m < 32; m <<= 1) v += __shfl_xor_sync(0xFFFFFFFFu, v, m);
        if (lane == j) s_w[wrp][j] = v;
    }
    __syncthreads();
    if (tid < K) {
        float s = 0.0f;
        #pragma unroll
        for (int w = 0; w < 8; w++) s += s_w[w][tid];
        s_invf[tid] = __fdividef(1.0f, s);
    }
    __syncthreads();

    float invf[K];
    #pragma unroll
    for (int j = 0; j < K; j++) invf[j] = s_invf[j];

    const int row0 = blockIdx.x * 512 + tid;

    #pragma unroll
    for (int r = 0; r < 2; r++) {
        const int row = row0 + r * 256;
        const float2* qr = (const float2*)(q + (size_t)row * K);
        float2* pr = (float2*)(p + (size_t)row * K);

        float w[K], s = 0.0f;
        #pragma unroll
        for (int m = 0; m < K / 2; m++) {
            float2 v = qr[m];
            float w0 = v.x * v.x * invf[2 * m];
            float w1 = v.y * v.y * invf[2 * m + 1];
            w[2 * m] = w0; w[2 * m + 1] = w1;
            s += w0 + w1;
        }
        const float inv = __fdividef(1.0f, s);
        #pragma unroll
        for (int m = 0; m < K / 2; m++) {
            float2 v;
            v.x = w[2 * m] * inv;
            v.y = w[2 * m + 1] * inv;
            pr[m] = v;
        }
    }
}

extern "C" void kernel_launch(void* const* d_in, const int* in_sizes, int n_in,
                              void* d_out, int out_size) {
    const float* z = (const float*)d_in[0];
    const float* c = (const float*)d_in[1];
    float* qout = (float*)d_out;
    float* pout = (float*)d_out + (size_t)BATCH * K;

    k_q<<<NBLK1, 256>>>(z, c, qout);
    k_p<<<BATCH / 512, 256>>>(qout, pout);
}

// round 3
// speedup vs baseline: 1.6775x; 1.6775x over previous
#include <cuda_runtime.h>

#define BATCH 262144
#define DIM   128
#define K     10
#define TILE_ROWS 64
#define THREADS1  64
#define NBLK1     512
#define TILES_PER_BLK (BATCH / TILE_ROWS / NBLK1)   // 8

// Per-block column-sum partials (fully overwritten each replay; no init needed).
__device__ float g_part[NBLK1][K];

typedef unsigned long long u64;

__device__ __forceinline__ u64 pack2(float lo, float hi) {
    u64 r; asm("mov.b64 %0, {%1, %2};" : "=l"(r) : "f"(lo), "f"(hi)); return r;
}
__device__ __forceinline__ void unpack2(u64 v, float& lo, float& hi) {
    asm("mov.b64 {%0, %1}, %2;" : "=f"(lo), "=f"(hi) : "l"(v));
}
__device__ __forceinline__ void fma2(u64& acc, u64 a, u64 b) {
    asm("fma.rn.f32x2 %0, %1, %2, %0;" : "+l"(acc) : "l"(a), "l"(b));
}

// Kernel 1: q = rownorm( 1/(1 + ||z-mu||^2) ) + per-block column partials.
// z staged through swizzled smem: global loads fully coalesced, then each
// thread owns one row in smem -> register dot products, NO inner shuffles.
__global__ __launch_bounds__(THREADS1) void k_q(
    const float* __restrict__ z,
    const float* __restrict__ c,
    float* __restrict__ qout)
{
    __shared__ float4 s_z[TILE_ROWS * 32];  // 32 KB, XOR-swizzled rows
    __shared__ float4 s_c[K][32];           // centers, 5120 B
    __shared__ float  s_cn[K];              // ||c_j||^2
    __shared__ float  s_part[2][K];

    const int tid  = threadIdx.x;
    const int lane = tid & 31;
    const int wrp  = tid >> 5;

    for (int i = tid; i < K * 32; i += THREADS1)
        ((float4*)s_c)[i] = ((const float4*)c)[i];
    __syncthreads();
    if (tid < K) {
        float s = 0.0f;
        #pragma unroll
        for (int d = 0; d < 32; d++) {
            float4 v = s_c[tid][d];
            s = fmaf(v.x, v.x, fmaf(v.y, v.y, fmaf(v.z, v.z, fmaf(v.w, v.w, s))));
        }
        s_cn[tid] = s;   // visible after the staging barrier below
    }

    float csum[K];
    #pragma unroll
    for (int j = 0; j < K; j++) csum[j] = 0.0f;

    const int r  = tid;        // this thread's row within every tile
    const int r7 = r & 7;

    for (int t = 0; t < TILES_PER_BLK; t++) {
        const int tile = blockIdx.x * TILES_PER_BLK + t;
        const float4* zg = (const float4*)z + (size_t)tile * TILE_ROWS * 32;

        // Stage: warp reads 32 consecutive float4 (512B contiguous) per iter.
        #pragma unroll
        for (int k2 = 0; k2 < 32; k2++) {
            const int g   = k2 * THREADS1 + tid;   // [0, 2048)
            const int row = g >> 5;
            const int i   = g & 31;
            s_z[row * 32 + (i ^ (row & 7))] = zg[g];
        }
        __syncthreads();

        u64 dot[K];
        #pragma unroll
        for (int j = 0; j < K; j++) dot[j] = 0ull;
        u64 zn = 0ull;

        #pragma unroll 8
        for (int i = 0; i < 32; i++) {
            float4 a = s_z[r * 32 + (i ^ r7)];
            u64 a01 = pack2(a.x, a.y), a23 = pack2(a.z, a.w);
            fma2(zn, a01, a01); fma2(zn, a23, a23);
            #pragma unroll
            for (int j = 0; j < K; j++) {
                float4 cc = s_c[j][i];               // broadcast LDS
                u64 c01 = pack2(cc.x, cc.y), c23 = pack2(cc.z, cc.w);
                fma2(dot[j], a01, c01); fma2(dot[j], a23, c23);
            }
        }

        float lo, hi;
        unpack2(zn, lo, hi);
        const float zz1 = 1.0f + (lo + hi);          // 1 + ||z||^2

        float q[K], rsum = 0.0f;
        #pragma unroll
        for (int j = 0; j < K; j++) {
            unpack2(dot[j], lo, hi);
            const float d = lo + hi;
            const float v = __fdividef(1.0f, fmaf(-2.0f, d, zz1 + s_cn[j]));
            q[j] = v; rsum += v;
        }
        const float inv = __fdividef(1.0f, rsum);

        const int row = tile * TILE_ROWS + r;
        float* orow = qout + (size_t)row * K;
        #pragma unroll
        for (int j = 0; j < K; j++) q[j] *= inv;
        #pragma unroll
        for (int m = 0; m < 5; m++) {
            float2 v; v.x = q[2 * m]; v.y = q[2 * m + 1];
            *(float2*)(orow + 2 * m) = v;
        }
        #pragma unroll
        for (int j = 0; j < K; j++) csum[j] += q[j];

        __syncthreads();   // protect s_z before next tile's staging
    }

    // One block-level reduction at the very end.
    #pragma unroll
    for (int j = 0; j < K; j++) {
        float v = csum[j];
        #pragma unroll
        for (int m = 16; m > 0; m >>= 1) v += __shfl_xor_sync(0xFFFFFFFFu, v, m);
        if (lane == 0) s_part[wrp][j] = v;
    }
    __syncthreads();
    if (tid < K) g_part[blockIdx.x][tid] = s_part[0][tid] + s_part[1][tid];
}

// Kernel 2: lightweight redundant colsum reduce (20KB from L2), then
// p = rownorm(q^2 / colsum), 1 row per thread.
__global__ __launch_bounds__(256) void k_p(
    const float* __restrict__ q,
    float* __restrict__ p)
{
    __shared__ float s_w[8][K];
    __shared__ float s_invf[K];

    const int tid  = threadIdx.x;
    const int lane = tid & 31;
    const int wrp  = tid >> 5;

    float acc[K];
    #pragma unroll
    for (int j = 0; j < K; j++)
        acc[j] = g_part[tid][j] + g_part[tid + 256][j];
    #pragma unroll
    for (int j = 0; j < K; j++) {
        float v = acc[j];
        #pragma unroll
        for (int m = 16; m > 0; m >>= 1) v += __shfl_xor_sync(0xFFFFFFFFu, v, m);
        if (lane == 0) s_w[wrp][j] = v;
    }
    __syncthreads();
    if (tid < K) {
        float s = 0.0f;
        #pragma unroll
        for (int w = 0; w < 8; w++) s += s_w[w][tid];
        s_invf[tid] = __fdividef(1.0f, s);
    }
    __syncthreads();

    float invf[K];
    #pragma unroll
    for (int j = 0; j < K; j++) invf[j] = s_invf[j];

    const int row = blockIdx.x * 256 + tid;
    const float2* qr = (const float2*)(q + (size_t)row * K);
    float2* pr = (float2*)(p + (size_t)row * K);

    float w[K], s = 0.0f;
    #pragma unroll
    for (int m = 0; m < K / 2; m++) {
        float2 v = qr[m];
        float w0 = v.x * v.x * invf[2 * m];
        float w1 = v.y * v.y * invf[2 * m + 1];
        w[2 * m] = w0; w[2 * m + 1] = w1;
        s += w0 + w1;
    }
    const float inv = __fdividef(1.0f, s);
    #pragma unroll
    for (int m = 0; m < K / 2; m++) {
        float2 v;
        v.x = w[2 * m] * inv;
        v.y = w[2 * m + 1] * inv;
        pr[m] = v;
    }
}

extern "C" void kernel_launch(void* const* d_in, const int* in_sizes, int n_in,
                              void* d_out, int out_size) {
    const float* z = (const float*)d_in[0];
    const float* c = (const float*)d_in[1];
    float* qout = (float*)d_out;
    float* pout = (float*)d_out + (size_t)BATCH * K;

    k_q<<<NBLK1, THREADS1>>>(z, c, qout);
    k_p<<<BATCH / 256, 256>>>(qout, pout);
}